// round 11
// baseline (speedup 1.0000x reference)
#include <cuda_runtime.h>
#include <cstdint>
#include <math.h>

#define T_STEPS 512
#define BATCH   64
#define IN0     256
#define HID     512
#define NBLK    128
#define NTHR    512
#define ROWS    32      // gate rows per block (8 hidden units x 4 gates)

// -------- static device scratch --------
__device__ float g_hs[(size_t)T_STEPS * HID * BATCH];   // layer0 outputs [t][k][64]
__device__ float g_xT[(size_t)T_STEPS * IN0 * BATCH];   // inputs transposed [t][k][64]
__device__ float g_hT[2 * HID * BATCH];                 // double-buffered h [buf][k][64]
__device__ unsigned g_prod[32];    // [bg][slot16]
__device__ unsigned g_cons[32];
__device__ unsigned g_fb;
__device__ unsigned g_fb_base;

// -------- packed f32x2 helpers --------
__device__ __forceinline__ unsigned long long dupf(float v) {
    unsigned long long r;
    asm("mov.b64 %0, {%1, %1};" : "=l"(r) : "f"(v));
    return r;
}
__device__ __forceinline__ void fma2(unsigned long long &d, unsigned long long a, unsigned long long b) {
    asm("fma.rn.f32x2 %0, %1, %2, %0;" : "+l"(d) : "l"(a), "l"(b));
}
__device__ __forceinline__ float sigf(float x) { return 1.0f / (1.0f + __expf(-x)); }
__device__ __forceinline__ float tanh_fast(float x) {
    float ax = fabsf(x);
    float e  = __expf(-2.0f * ax);
    float r  = __fdividef(1.0f - e, 1.0f + e);
    return copysignf(r, x);
}

// -------- sync primitives --------
__device__ __forceinline__ void arrive(unsigned* ctr) {
    asm volatile("red.release.gpu.global.add.u32 [%0], 1;" :: "l"(ctr) : "memory");
}
__device__ __forceinline__ void wait_ge(const unsigned* ctr, unsigned target) {
    unsigned v;
    do {
        asm volatile("ld.acquire.gpu.global.u32 %0, [%1];" : "=r"(v) : "l"(ctr) : "memory");
    } while ((int)(v - target) < 0);
}
__device__ __forceinline__ void full_barrier(unsigned &expect) {
    __syncthreads();
    if (threadIdx.x == 0) {
        arrive(&g_fb);
        expect += NBLK;
        wait_ge(&g_fb, expect);
    }
    __syncthreads();
}

// -------- cp.async --------
__device__ __forceinline__ void cp16(uint32_t sm, const float* g) {
    asm volatile("cp.async.cg.shared.global [%0], [%1], 16;" :: "r"(sm), "l"(g));
}
__device__ __forceinline__ void cp_commit() { asm volatile("cp.async.commit_group;" ::: "memory"); }
template<int N>
__device__ __forceinline__ void cp_wait() { asm volatile("cp.async.wait_group %0;" :: "n"(N) : "memory"); }

// one chunk = 128 k x 32 b = 16KB; 2 cp16 per thread (512 threads)
__device__ __forceinline__ void issue_chunk(float* smdst, const float* src, int tid) {
    uint32_t s = (uint32_t)__cvta_generic_to_shared(smdst);
#pragma unroll
    for (int q = 0; q < 2; ++q) {
        int i4 = tid + q * NTHR;          // 0..1023
        int k   = i4 >> 3;                // 0..127
        int off = i4 & 7;                 // 16B units within 128B row
        cp16(s + i4 * 16, src + k * 64 + off * 4);
    }
    cp_commit();
}

// smem layout (floats)
//  w_s   [1024][32]        = 32768
//  hbuf  4 x [128][32]     = 16384
//  red   [128 u64 rows][33 u64] = 8448 floats
//  bias  [32]
#define OFF_W    0
#define OFF_HBUF 32768
#define OFF_RED  (32768 + 16384)
#define OFF_BIAS (OFF_RED + 8448)
#define SMEM_FLOATS (OFF_BIAS + 32)

// -------- inner chunk compute: 16 kk, tile 2 row-pairs (4 rows) x 4 batch --------
// hb = slot + kc*16*32 + bp*4 ; wp = w_s + (c*128 + kc*16)*32 + rw*16 + rg*4
__device__ __forceinline__ void compute_chunk(const float* hb, const float* wp,
                                              unsigned long long acc[8])
{
    float4 h4 = *(const float4*)hb;
    ulonglong2 wA = *(const ulonglong2*)wp;
#pragma unroll
    for (int kk = 0; kk < 16; ++kk) {
        float4     h4n = *(const float4*)(hb + (kk + 1) * 32);
        ulonglong2 wAn = *(const ulonglong2*)(wp + (kk + 1) * 32);

        unsigned long long hd0 = dupf(h4.x), hd1 = dupf(h4.y),
                           hd2 = dupf(h4.z), hd3 = dupf(h4.w);

        fma2(acc[0], wA.x, hd0); fma2(acc[1], wA.x, hd1);
        fma2(acc[2], wA.x, hd2); fma2(acc[3], wA.x, hd3);
        fma2(acc[4], wA.y, hd0); fma2(acc[5], wA.y, hd1);
        fma2(acc[6], wA.y, hd2); fma2(acc[7], wA.y, hd3);

        h4 = h4n; wA = wAn;
    }
}

template<int K_IN>
__device__ void run_layer(int layer, const float* __restrict__ xT,
                          const float* __restrict__ h0l, const float* __restrict__ c0l,
                          const float* __restrict__ w_ih, const float* __restrict__ w_hh,
                          const float* __restrict__ b_ih, const float* __restrict__ b_hh,
                          float* __restrict__ out, float* smem, unsigned &fb_expect)
{
    constexpr int XC = K_IN / 128;           // x chunks (2 or 4)
    constexpr int NC = XC + 4;               // total chunks (6 or 8)
    constexpr int K_TOT = K_IN + HID;

    float* w_s   = smem + OFF_W;
    float* hbuf  = smem + OFF_HBUF;
    float* red_f = smem + OFF_RED;
    unsigned long long* red_u = (unsigned long long*)red_f;
    float* bias_s = smem + OFF_BIAS;

    const int tid = threadIdx.x;
    const int bg  = blockIdx.x & 1;          // batch half
    const int hg  = blockIdx.x >> 1;         // hidden group (8 units)

    // compute roles: 16 warps = kc(8 K-split) x rw(2 row-half)
    const int wid = tid >> 5;
    const int kc  = wid >> 1;                // 0..7
    const int rw  = wid & 1;                 // 0..1
    const int rg  = (tid >> 3) & 3;          // 0..3 (4-row groups within half)
    const int bp  = tid & 7;                 // 0..7 (4-batch groups)

    // epilogue roles (tid < 256): one cell each
    const int jj = tid >> 5;                 // 0..7 (valid when tid<256)
    const int bl = tid & 31;                 // local batch

    unsigned* prod = g_prod + bg * 16;
    unsigned* cons = g_cons + bg * 16;

    // ---- init ----
    full_barrier(fb_expect);
    if (tid < 32) { g_prod[tid] = 0; g_cons[tid] = 0; }

#pragma unroll 1
    for (int rr = 0; rr < ROWS; ++rr) {
        int row = (rr >> 3) * HID + hg * 8 + (rr & 7);    // gate*H + j
        for (int kg = tid; kg < K_TOT; kg += NTHR) {
            float v = (kg < K_IN) ? w_ih[row * K_IN + kg]
                                  : w_hh[row * HID + (kg - K_IN)];
            w_s[kg * 32 + rr] = v;
        }
    }
    if (tid < 32) {
        int row = (tid >> 3) * HID + hg * 8 + (tid & 7);
        bias_s[tid] = b_ih[row] + b_hh[row];
    }
    float c_reg = 0.0f;
    if (tid < 256) {
        int j = hg * 8 + jj, b = bg * 32 + bl;
        c_reg = c0l[b * HID + j];
        g_hT[j * 64 + b] = h0l[b * HID + j];      // buffer 0
    }
    full_barrier(fb_expect);

    // prefetch step-0 x chunks 0,1
    {
        const float* x0 = xT + bg * 32;
        issue_chunk(hbuf + 0 * 4096, x0, tid);
        issue_chunk(hbuf + 1 * 4096, x0 + (size_t)128 * 64, tid);
    }

    for (int t = 0; t < T_STEPS; ++t) {
        const float* xt   = xT + (size_t)t * K_IN * 64 + bg * 32;
        const float* hcur = g_hT + (t & 1) * HID * 64 + bg * 32;

        unsigned long long acc[8];
#pragma unroll
        for (int j = 0; j < 8; ++j) acc[j] = 0ull;

        const int hb_off = kc * 16 * 32 + bp * 4;
        const int wp_off = rw * 16 + rg * 4;

#pragma unroll 1
        for (int c = 0; c < NC; ++c) {
            if (c + 2 < NC) {
                if (c + 2 == XC && t > 0) {
                    // h_t must be published by all 64 blocks of this half
                    if (tid == 0) {
                        unsigned rounds = (unsigned)(t >> 4) + 1u - (((t & 15) == 0) ? 1u : 0u);
                        wait_ge(&prod[t & 15], 64u * rounds);
                    }
                    __syncthreads();
                }
                const float* src = (c + 2 < XC) ? (xt + (size_t)(c + 2) * 128 * 64)
                                                : (hcur + (size_t)(c + 2 - XC) * 128 * 64);
                issue_chunk(hbuf + ((c + 2) & 3) * 4096, src, tid);
                cp_wait<2>();
            } else if (c + 1 < NC) cp_wait<1>();
            else                   cp_wait<0>();
            __syncthreads();
            compute_chunk(hbuf + (c & 3) * 4096 + hb_off,
                          w_s + (c * 128 + kc * 16) * 32 + wp_off, acc);
        }
        // all h_t bytes landed in smem
        if (tid == 0) arrive(&cons[t & 15]);

        // ---- reduction: store packed u64 partials ----
        // u64 pair-row = kc*16 + rw*8 + rg*2 + p ; col = bp*4 + bi, pitch 33
#pragma unroll
        for (int p = 0; p < 2; ++p) {
#pragma unroll
            for (int bi = 0; bi < 4; ++bi)
                red_u[(kc * 16 + rw * 8 + rg * 2 + p) * 33 + bp * 4 + bi] = acc[p * 4 + bi];
        }
        __syncthreads();

        // prefetch next step's x chunks early (slots 0,1 last computed at c=NC-4,NC-3)
        if (t + 1 < T_STEPS) {
            const float* xn = xT + (size_t)(t + 1) * K_IN * 64 + bg * 32;
            issue_chunk(hbuf + 0 * 4096, xn, tid);
            issue_chunk(hbuf + 1 * 4096, xn + (size_t)128 * 64, tid);
        }

        // ---- gates: 1 cell per thread (tid < 256) ----
        // red_f pair-row r maps rows 2r,2r+1; row rr (0..31 = gate*8+jj? no: rr
        // within block = rw*16+rg*4+... covered identically to R6 since the
        // pair-row space is the same: row rr lives at pair-row rr>>1, float lane
        // (b*2 + rr&1) in the 66-float row.
        float hn = 0.0f, cn = 0.0f;
        if (tid < 256) {
            float s0 = bias_s[jj], s1 = bias_s[8 + jj], s2 = bias_s[16 + jj], s3 = bias_s[24 + jj];
            const int lane = bl * 2 + (jj & 1);
            const int rphi = jj >> 1;
#pragma unroll
            for (int k8 = 0; k8 < 8; ++k8) {
                s0 += red_f[(k8 * 16 +      rphi) * 66 + lane];
                s1 += red_f[(k8 * 16 +  4 + rphi) * 66 + lane];
                s2 += red_f[(k8 * 16 +  8 + rphi) * 66 + lane];
                s3 += red_f[(k8 * 16 + 12 + rphi) * 66 + lane];
            }
            cn = sigf(s1) * c_reg + sigf(s0) * tanh_fast(s2);
            hn = sigf(s3) * tanh_fast(cn);
            c_reg = cn;
        }

        // ---- wait: this half consumed h_{t-1} before overwriting its buffer ----
        if (t >= 1) {
            if (tid == 0) {
                unsigned rounds = (unsigned)((t - 1) >> 4) + 1u;
                wait_ge(&cons[(t - 1) & 15], 64u * rounds);
            }
            __syncthreads();
        }

        // ---- write h_{t+1} ----
        if (tid < 256) {
            int j = hg * 8 + jj, b = bg * 32 + bl;
            g_hT[((t + 1) & 1) * HID * 64 + j * 64 + b] = hn;
            if (layer == 0)
                g_hs[((size_t)t * HID + j) * 64 + b] = hn;
            if (t == T_STEPS - 1) {
                out[layer * BATCH * HID + b * HID + j] = hn;
                out[2 * BATCH * HID + layer * BATCH * HID + b * HID + j] = cn;
            }
        }
        __syncthreads();
        if (tid == 0) arrive(&prod[(t + 1) & 15]);
    }

    full_barrier(fb_expect);
}

__global__ void __launch_bounds__(NTHR, 1)
lstm_scan_kernel(const float* __restrict__ h0,
                 const float* __restrict__ c0,
                 const float* __restrict__ w_ih0, const float* __restrict__ w_hh0,
                 const float* __restrict__ b_ih0, const float* __restrict__ b_hh0,
                 const float* __restrict__ w_ih1, const float* __restrict__ w_hh1,
                 const float* __restrict__ b_ih1, const float* __restrict__ b_hh1,
                 float* __restrict__ out)
{
    extern __shared__ float smem[];
    unsigned fb_expect = g_fb_base;

    run_layer<IN0>(0, g_xT, h0, c0, w_ih0, w_hh0, b_ih0, b_hh0, out, smem, fb_expect);
    run_layer<HID>(1, g_hs, h0 + BATCH * HID, c0 + BATCH * HID,
                   w_ih1, w_hh1, b_ih1, b_hh1, out, smem, fb_expect);

    if (blockIdx.x == 0 && threadIdx.x == 0)
        g_fb_base = fb_expect;
}

// -------- prepass: transpose inputs to g_xT AND copy passthrough to out tail --------
__global__ void prep_kernel(const float* __restrict__ in, float* __restrict__ out_tail)
{
    __shared__ float tile[32][33];
    int t  = blockIdx.x;
    int i0 = blockIdx.y * 32;
    int b0 = blockIdx.z * 32;
    int tx = threadIdx.x, ty = threadIdx.y;   // 32 x 8
    const float* ip = in + (size_t)t * BATCH * IN0;
    float* cp = out_tail + (size_t)t * BATCH * IN0;
    float* op = g_xT + (size_t)t * IN0 * BATCH;
#pragma unroll
    for (int yy = 0; yy < 32; yy += 8) {
        float v = ip[(b0 + ty + yy) * IN0 + i0 + tx];
        tile[ty + yy][tx] = v;
        cp[(b0 + ty + yy) * IN0 + i0 + tx] = v;
    }
    __syncthreads();
#pragma unroll
    for (int yy = 0; yy < 32; yy += 8)
        op[(i0 + ty + yy) * BATCH + b0 + tx] = tile[tx][ty + yy];
}

extern "C" void kernel_launch(void* const* d_in, const int* in_sizes, int n_in,
                              void* d_out, int out_size)
{
    const float* inputs = (const float*)d_in[0];
    const float* h0     = (const float*)d_in[1];
    const float* c0     = (const float*)d_in[2];
    const float* w_ih0  = (const float*)d_in[3];
    const float* w_hh0  = (const float*)d_in[4];
    const float* b_ih0  = (const float*)d_in[5];
    const float* b_hh0  = (const float*)d_in[6];
    const float* w_ih1  = (const float*)d_in[7];
    const float* w_hh1  = (const float*)d_in[8];
    const float* b_ih1  = (const float*)d_in[9];
    const float* b_hh1  = (const float*)d_in[10];
    float* out = (float*)d_out;

    (void)in_sizes; (void)n_in; (void)out_size;

    cudaFuncSetAttribute(lstm_scan_kernel,
                         cudaFuncAttributeMaxDynamicSharedMemorySize,
                         SMEM_FLOATS * (int)sizeof(float));

    prep_kernel<<<dim3(T_STEPS, IN0 / 32, BATCH / 32), dim3(32, 8)>>>(
        inputs, out + 4 * BATCH * HID);

    lstm_scan_kernel<<<NBLK, NTHR, SMEM_FLOATS * sizeof(float)>>>(
        h0, c0,
        w_ih0, w_hh0, b_ih0, b_hh0,
        w_ih1, w_hh1, b_ih1, b_hh1,
        out);
}

// round 12
// speedup vs baseline: 1.2889x; 1.2889x over previous
#include <cuda_runtime.h>
#include <cstdint>
#include <math.h>

#define T_STEPS 512
#define BATCH   64
#define IN0     256
#define HID     512
#define NBLK    128
#define NTHR    256
#define ROWS    32      // gate rows per block (8 hidden units x 4 gates)

// -------- static device scratch --------
__device__ float g_hs[(size_t)T_STEPS * HID * BATCH];   // layer0 outputs [t][k][64]
__device__ float g_xT[(size_t)T_STEPS * IN0 * BATCH];   // inputs transposed [t][k][64]
__device__ float g_hT[2 * HID * BATCH];                 // double-buffered h [buf][k][64]
__device__ unsigned g_prod[32];    // [bg][slot16]
__device__ unsigned g_cons[32];
__device__ unsigned g_fb;
__device__ unsigned g_fb_base;

// -------- packed f32x2 helpers --------
__device__ __forceinline__ unsigned long long dupf(float v) {
    unsigned long long r;
    asm("mov.b64 %0, {%1, %1};" : "=l"(r) : "f"(v));
    return r;
}
__device__ __forceinline__ void fma2(unsigned long long &d, unsigned long long a, unsigned long long b) {
    asm("fma.rn.f32x2 %0, %1, %2, %0;" : "+l"(d) : "l"(a), "l"(b));
}
__device__ __forceinline__ float sigf(float x) { return 1.0f / (1.0f + __expf(-x)); }
__device__ __forceinline__ float tanh_fast(float x) {
    float ax = fabsf(x);
    float e  = __expf(-2.0f * ax);
    float r  = __fdividef(1.0f - e, 1.0f + e);
    return copysignf(r, x);
}

// -------- sync primitives --------
__device__ __forceinline__ void arrive(unsigned* ctr) {
    asm volatile("red.release.gpu.global.add.u32 [%0], 1;" :: "l"(ctr) : "memory");
}
__device__ __forceinline__ void wait_ge(const unsigned* ctr, unsigned target) {
    unsigned v;
    do {
        asm volatile("ld.acquire.gpu.global.u32 %0, [%1];" : "=r"(v) : "l"(ctr) : "memory");
    } while ((int)(v - target) < 0);
}
__device__ __forceinline__ void full_barrier(unsigned &expect) {
    __syncthreads();
    if (threadIdx.x == 0) {
        arrive(&g_fb);
        expect += NBLK;
        wait_ge(&g_fb, expect);
    }
    __syncthreads();
}

// -------- cp.async --------
__device__ __forceinline__ void cp16(uint32_t sm, const float* g) {
    asm volatile("cp.async.cg.shared.global [%0], [%1], 16;" :: "r"(sm), "l"(g));
}
__device__ __forceinline__ void cp_commit() { asm volatile("cp.async.commit_group;" ::: "memory"); }
template<int N>
__device__ __forceinline__ void cp_wait() { asm volatile("cp.async.wait_group %0;" :: "n"(N) : "memory"); }

// one chunk = 128 k x 32 b = 16KB; 4 cp16 per thread (256 threads)
__device__ __forceinline__ void issue_chunk(float* smdst, const float* src, int tid) {
    uint32_t s = (uint32_t)__cvta_generic_to_shared(smdst);
#pragma unroll
    for (int q = 0; q < 4; ++q) {
        int i4 = tid + q * NTHR;          // 0..1023
        int k   = i4 >> 3;                // 0..127
        int off = i4 & 7;                 // 16B units within 128B row
        cp16(s + i4 * 16, src + k * 64 + off * 4);
    }
    cp_commit();
}

// smem layout (floats)
//  w_s   [1024][32]        = 32768
//  hbuf  4 x [128][32]     = 16384
//  red   [128 u64 rows][33 u64] = 8448 floats
//  bias  [32]
#define OFF_W    0
#define OFF_HBUF 32768
#define OFF_RED  (32768 + 16384)
#define OFF_BIAS (OFF_RED + 8448)
#define SMEM_FLOATS (OFF_BIAS + 32)

// -------- inner chunk compute: 16 kk, tile 4 row-pairs x 4 batch --------
__device__ __forceinline__ void compute_chunk(const float* hb, const float* wp,
                                              unsigned long long acc[16])
{
    float4 h4 = *(const float4*)hb;
    ulonglong2 wA = *(const ulonglong2*)wp;
    ulonglong2 wB = *(const ulonglong2*)(wp + 4);
#pragma unroll
    for (int kk = 0; kk < 16; ++kk) {
        float4     h4n = *(const float4*)(hb + (kk + 1) * 32);
        ulonglong2 wAn = *(const ulonglong2*)(wp + (kk + 1) * 32);
        ulonglong2 wBn = *(const ulonglong2*)(wp + (kk + 1) * 32 + 4);

        unsigned long long hd0 = dupf(h4.x), hd1 = dupf(h4.y),
                           hd2 = dupf(h4.z), hd3 = dupf(h4.w);

        fma2(acc[ 0], wA.x, hd0); fma2(acc[ 1], wA.x, hd1); fma2(acc[ 2], wA.x, hd2); fma2(acc[ 3], wA.x, hd3);
        fma2(acc[ 4], wA.y, hd0); fma2(acc[ 5], wA.y, hd1); fma2(acc[ 6], wA.y, hd2); fma2(acc[ 7], wA.y, hd3);
        fma2(acc[ 8], wB.x, hd0); fma2(acc[ 9], wB.x, hd1); fma2(acc[10], wB.x, hd2); fma2(acc[11], wB.x, hd3);
        fma2(acc[12], wB.y, hd0); fma2(acc[13], wB.y, hd1); fma2(acc[14], wB.y, hd2); fma2(acc[15], wB.y, hd3);

        h4 = h4n; wA = wAn; wB = wBn;
    }
}

template<int K_IN>
__device__ void run_layer(int layer, const float* __restrict__ xT,
                          const float* __restrict__ h0l, const float* __restrict__ c0l,
                          const float* __restrict__ w_ih, const float* __restrict__ w_hh,
                          const float* __restrict__ b_ih, const float* __restrict__ b_hh,
                          float* __restrict__ out, float* smem, unsigned &fb_expect)
{
    constexpr int XC = K_IN / 128;           // x chunks (2 or 4)
    constexpr int NC = XC + 4;               // total chunks (6 or 8)
    constexpr int NP = NC / 2;               // chunk pairs (3 or 4)
    constexpr int XP = XC / 2;               // x pairs (1 or 2)
    constexpr int K_TOT = K_IN + HID;

    float* w_s   = smem + OFF_W;
    float* hbuf  = smem + OFF_HBUF;
    float* red_f = smem + OFF_RED;
    unsigned long long* red_u = (unsigned long long*)red_f;
    float* bias_s = smem + OFF_BIAS;

    const int tid = threadIdx.x;
    const int bg  = blockIdx.x & 1;          // batch half
    const int hg  = blockIdx.x >> 1;         // hidden group (8 units)

    // compute roles: warp = split-K group
    const int kc = tid >> 5;                 // 0..7
    const int rg = (tid >> 3) & 3;           // 0..3 (row-pair quads)
    const int bp = tid & 7;                  // 0..7 (4-batch groups)

    // epilogue roles: one cell each
    const int jj = tid >> 5;                 // 0..7 hidden unit in group
    const int bl = tid & 31;                 // local batch

    unsigned* prod = g_prod + bg * 16;
    unsigned* cons = g_cons + bg * 16;

    // ---- init ----
    full_barrier(fb_expect);
    if (tid < 32) { g_prod[tid] = 0; g_cons[tid] = 0; }

#pragma unroll 1
    for (int rr = 0; rr < ROWS; ++rr) {
        int row = (rr >> 3) * HID + hg * 8 + (rr & 7);    // gate*H + j
        for (int kg = tid; kg < K_TOT; kg += NTHR) {
            float v = (kg < K_IN) ? w_ih[row * K_IN + kg]
                                  : w_hh[row * HID + (kg - K_IN)];
            w_s[kg * 32 + rr] = v;
        }
    }
    if (tid < 32) {
        int row = (tid >> 3) * HID + hg * 8 + (tid & 7);
        bias_s[tid] = b_ih[row] + b_hh[row];
    }
    float c_reg;
    {
        int j = hg * 8 + jj, b = bg * 32 + bl;
        c_reg = c0l[b * HID + j];
        g_hT[j * 64 + b] = h0l[b * HID + j];      // buffer 0
    }
    full_barrier(fb_expect);

    // prefetch step-0 pair 0 (x chunks 0,1)
    {
        const float* x0 = xT + bg * 32;
        issue_chunk(hbuf + 0 * 4096, x0, tid);
        issue_chunk(hbuf + 1 * 4096, x0 + (size_t)128 * 64, tid);
    }

    for (int t = 0; t < T_STEPS; ++t) {
        const float* xt   = xT + (size_t)t * K_IN * 64 + bg * 32;
        const float* hcur = g_hT + (t & 1) * HID * 64 + bg * 32;

        unsigned long long acc[16];
#pragma unroll
        for (int j = 0; j < 16; ++j) acc[j] = 0ull;

        const int hb_off = kc * 16 * 32 + bp * 4;

#pragma unroll 1
        for (int p = 0; p < NP; ++p) {
            if (p + 1 < NP) {
                if (p + 1 == XP && t > 0) {
                    // h_t must be published by all 64 blocks of this half
                    if (tid == 0) {
                        unsigned rounds = (unsigned)(t >> 4) + 1u - (((t & 15) == 0) ? 1u : 0u);
                        wait_ge(&prod[t & 15], 64u * rounds);
                    }
                    __syncthreads();
                }
                // issue pair p+1 (chunks 2(p+1), 2(p+1)+1)
                {
                    int c0 = 2 * (p + 1);
                    int c1 = c0 + 1;
                    const float* s0 = (c0 < XC) ? (xt + (size_t)c0 * 128 * 64)
                                                : (hcur + (size_t)(c0 - XC) * 128 * 64);
                    const float* s1 = (c1 < XC) ? (xt + (size_t)c1 * 128 * 64)
                                                : (hcur + (size_t)(c1 - XC) * 128 * 64);
                    issue_chunk(hbuf + (c0 & 3) * 4096, s0, tid);
                    issue_chunk(hbuf + (c1 & 3) * 4096, s1, tid);
                }
                cp_wait<2>();
            } else {
                cp_wait<0>();
            }
            __syncthreads();
            // compute pair p: 32 kk straight-line
            compute_chunk(hbuf + ((2 * p) & 3) * 4096 + hb_off,
                          w_s + ((2 * p) * 128 + kc * 16) * 32 + rg * 8, acc);
            compute_chunk(hbuf + ((2 * p + 1) & 3) * 4096 + hb_off,
                          w_s + ((2 * p + 1) * 128 + kc * 16) * 32 + rg * 8, acc);
        }
        // all h_t bytes landed in smem
        if (tid == 0) arrive(&cons[t & 15]);

        // ---- reduction: store packed u64 partials ----
#pragma unroll
        for (int rp = 0; rp < 4; ++rp) {
#pragma unroll
            for (int bi = 0; bi < 4; ++bi)
                red_u[(kc * 16 + rg * 4 + rp) * 33 + bp * 4 + bi] = acc[rp * 4 + bi];
        }
        __syncthreads();

        // ---- gates: 1 cell per thread ----
        float hn, cn;
        {
            float s0 = bias_s[jj], s1 = bias_s[8 + jj], s2 = bias_s[16 + jj], s3 = bias_s[24 + jj];
            const int lane = bl * 2 + (jj & 1);
            const int rphi = jj >> 1;
#pragma unroll
            for (int k8 = 0; k8 < 8; ++k8) {
                s0 += red_f[(k8 * 16 +      rphi) * 66 + lane];
                s1 += red_f[(k8 * 16 +  4 + rphi) * 66 + lane];
                s2 += red_f[(k8 * 16 +  8 + rphi) * 66 + lane];
                s3 += red_f[(k8 * 16 + 12 + rphi) * 66 + lane];
            }
            cn = sigf(s1) * c_reg + sigf(s0) * tanh_fast(s2);
            hn = sigf(s3) * tanh_fast(cn);
            c_reg = cn;
        }

        // prefetch next step's pair 0 (slots 0,1 last computed at pair NP-2)
        if (t + 1 < T_STEPS) {
            const float* xn = xT + (size_t)(t + 1) * K_IN * 64 + bg * 32;
            issue_chunk(hbuf + 0 * 4096, xn, tid);
            issue_chunk(hbuf + 1 * 4096, xn + (size_t)128 * 64, tid);
        }

        // ---- wait: this half consumed h_{t-1} before overwriting its buffer ----
        if (t >= 1) {
            if (tid == 0) {
                unsigned rounds = (unsigned)((t - 1) >> 4) + 1u;
                wait_ge(&cons[(t - 1) & 15], 64u * rounds);
            }
            __syncthreads();
        }

        // ---- write h_{t+1} ----
        {
            int j = hg * 8 + jj, b = bg * 32 + bl;
            g_hT[((t + 1) & 1) * HID * 64 + j * 64 + b] = hn;
            if (layer == 0)
                g_hs[((size_t)t * HID + j) * 64 + b] = hn;
            if (t == T_STEPS - 1) {
                out[layer * BATCH * HID + b * HID + j] = hn;
                out[2 * BATCH * HID + layer * BATCH * HID + b * HID + j] = cn;
            }
        }
        __syncthreads();
        if (tid == 0) arrive(&prod[(t + 1) & 15]);
    }

    full_barrier(fb_expect);
}

__global__ void __launch_bounds__(NTHR, 1)
lstm_scan_kernel(const float* __restrict__ h0,
                 const float* __restrict__ c0,
                 const float* __restrict__ w_ih0, const float* __restrict__ w_hh0,
                 const float* __restrict__ b_ih0, const float* __restrict__ b_hh0,
                 const float* __restrict__ w_ih1, const float* __restrict__ w_hh1,
                 const float* __restrict__ b_ih1, const float* __restrict__ b_hh1,
                 float* __restrict__ out)
{
    extern __shared__ float smem[];
    unsigned fb_expect = g_fb_base;

    run_layer<IN0>(0, g_xT, h0, c0, w_ih0, w_hh0, b_ih0, b_hh0, out, smem, fb_expect);
    run_layer<HID>(1, g_hs, h0 + BATCH * HID, c0 + BATCH * HID,
                   w_ih1, w_hh1, b_ih1, b_hh1, out, smem, fb_expect);

    if (blockIdx.x == 0 && threadIdx.x == 0)
        g_fb_base = fb_expect;
}

// -------- prepass: transpose inputs to g_xT AND copy passthrough to out tail --------
__global__ void prep_kernel(const float* __restrict__ in, float* __restrict__ out_tail)
{
    __shared__ float tile[32][33];
    int t  = blockIdx.x;
    int i0 = blockIdx.y * 32;
    int b0 = blockIdx.z * 32;
    int tx = threadIdx.x, ty = threadIdx.y;   // 32 x 8
    const float* ip = in + (size_t)t * BATCH * IN0;
    float* cp = out_tail + (size_t)t * BATCH * IN0;
    float* op = g_xT + (size_t)t * IN0 * BATCH;
#pragma unroll
    for (int yy = 0; yy < 32; yy += 8) {
        float v = ip[(b0 + ty + yy) * IN0 + i0 + tx];
        tile[ty + yy][tx] = v;
        cp[(b0 + ty + yy) * IN0 + i0 + tx] = v;
    }
    __syncthreads();
#pragma unroll
    for (int yy = 0; yy < 32; yy += 8)
        op[(i0 + ty + yy) * BATCH + b0 + tx] = tile[tx][ty + yy];
}

extern "C" void kernel_launch(void* const* d_in, const int* in_sizes, int n_in,
                              void* d_out, int out_size)
{
    const float* inputs = (const float*)d_in[0];
    const float* h0     = (const float*)d_in[1];
    const float* c0     = (const float*)d_in[2];
    const float* w_ih0  = (const float*)d_in[3];
    const float* w_hh0  = (const float*)d_in[4];
    const float* b_ih0  = (const float*)d_in[5];
    const float* b_hh0  = (const float*)d_in[6];
    const float* w_ih1  = (const float*)d_in[7];
    const float* w_hh1  = (const float*)d_in[8];
    const float* b_ih1  = (const float*)d_in[9];
    const float* b_hh1  = (const float*)d_in[10];
    float* out = (float*)d_out;

    (void)in_sizes; (void)n_in; (void)out_size;

    cudaFuncSetAttribute(lstm_scan_kernel,
                         cudaFuncAttributeMaxDynamicSharedMemorySize,
                         SMEM_FLOATS * (int)sizeof(float));

    prep_kernel<<<dim3(T_STEPS, IN0 / 32, BATCH / 32), dim3(32, 8)>>>(
        inputs, out + 4 * BATCH * HID);

    lstm_scan_kernel<<<NBLK, NTHR, SMEM_FLOATS * sizeof(float)>>>(
        h0, c0,
        w_ih0, w_hh0, b_ih0, b_hh0,
        w_ih1, w_hh1, b_ih1, b_hh1,
        out);
}

// round 13
// speedup vs baseline: 1.4447x; 1.1209x over previous
#include <cuda_runtime.h>
#include <cstdint>
#include <math.h>

#define T_STEPS 512
#define BATCH   64
#define IN0     256
#define HID     512
#define NBLK    128
#define NTHR    256
#define ROWS    32      // gate rows per block (8 hidden units x 4 gates)

// -------- static device scratch --------
__device__ float g_hs[(size_t)T_STEPS * HID * BATCH];   // layer0 outputs [t][k][64]
__device__ float g_xT[(size_t)T_STEPS * IN0 * BATCH];   // inputs transposed [t][k][64]
__device__ float g_hT[2 * HID * BATCH];                 // double-buffered h [buf][k][64]
__device__ unsigned g_prod[32];    // [bg][slot16]
__device__ unsigned g_fb;
__device__ unsigned g_fb_base;

// -------- packed f32x2 helpers --------
__device__ __forceinline__ unsigned long long dupf(float v) {
    unsigned long long r;
    asm("mov.b64 %0, {%1, %1};" : "=l"(r) : "f"(v));
    return r;
}
__device__ __forceinline__ void fma2(unsigned long long &d, unsigned long long a, unsigned long long b) {
    asm("fma.rn.f32x2 %0, %1, %2, %0;" : "+l"(d) : "l"(a), "l"(b));
}
__device__ __forceinline__ float sigf(float x) { return 1.0f / (1.0f + __expf(-x)); }
__device__ __forceinline__ float tanh_fast(float x) {
    float ax = fabsf(x);
    float e  = __expf(-2.0f * ax);
    float r  = __fdividef(1.0f - e, 1.0f + e);
    return copysignf(r, x);
}

// -------- sync primitives --------
__device__ __forceinline__ void arrive(unsigned* ctr) {
    asm volatile("red.release.gpu.global.add.u32 [%0], 1;" :: "l"(ctr) : "memory");
}
__device__ __forceinline__ void wait_ge(const unsigned* ctr, unsigned target) {
    unsigned v;
    do {
        asm volatile("ld.acquire.gpu.global.u32 %0, [%1];" : "=r"(v) : "l"(ctr) : "memory");
    } while ((int)(v - target) < 0);
}
__device__ __forceinline__ void full_barrier(unsigned &expect) {
    __syncthreads();
    if (threadIdx.x == 0) {
        arrive(&g_fb);
        expect += NBLK;
        wait_ge(&g_fb, expect);
    }
    __syncthreads();
}

// -------- cp.async --------
__device__ __forceinline__ void cp16(uint32_t sm, const float* g) {
    asm volatile("cp.async.cg.shared.global [%0], [%1], 16;" :: "r"(sm), "l"(g));
}
__device__ __forceinline__ void cp_commit() { asm volatile("cp.async.commit_group;" ::: "memory"); }
template<int N>
__device__ __forceinline__ void cp_wait() { asm volatile("cp.async.wait_group %0;" :: "n"(N) : "memory"); }

// one chunk = 128 k x 32 b = 16KB; 4 cp16 per thread (256 threads)
__device__ __forceinline__ void issue_chunk(float* smdst, const float* src, int tid) {
    uint32_t s = (uint32_t)__cvta_generic_to_shared(smdst);
#pragma unroll
    for (int q = 0; q < 4; ++q) {
        int i4 = tid + q * NTHR;          // 0..1023
        int k   = i4 >> 3;                // 0..127
        int off = i4 & 7;                 // 16B units within 128B row
        cp16(s + i4 * 16, src + k * 64 + off * 4);
    }
    cp_commit();
}

// smem layout (floats)
#define OFF_W    0
#define OFF_HBUF 32768
#define OFF_RED  (32768 + 16384)
#define OFF_BIAS (OFF_RED + 8448)
#define SMEM_FLOATS (OFF_BIAS + 32)

// -------- inner chunk compute: 16 kk, tile 4 row-pairs x 4 batch --------
__device__ __forceinline__ void compute_chunk(const float* hb, const float* wp,
                                              unsigned long long acc[16])
{
    float4 h4 = *(const float4*)hb;
    ulonglong2 wA = *(const ulonglong2*)wp;
    ulonglong2 wB = *(const ulonglong2*)(wp + 4);
#pragma unroll
    for (int kk = 0; kk < 16; ++kk) {
        float4     h4n = *(const float4*)(hb + (kk + 1) * 32);
        ulonglong2 wAn = *(const ulonglong2*)(wp + (kk + 1) * 32);
        ulonglong2 wBn = *(const ulonglong2*)(wp + (kk + 1) * 32 + 4);

        unsigned long long hd0 = dupf(h4.x), hd1 = dupf(h4.y),
                           hd2 = dupf(h4.z), hd3 = dupf(h4.w);

        fma2(acc[ 0], wA.x, hd0); fma2(acc[ 1], wA.x, hd1); fma2(acc[ 2], wA.x, hd2); fma2(acc[ 3], wA.x, hd3);
        fma2(acc[ 4], wA.y, hd0); fma2(acc[ 5], wA.y, hd1); fma2(acc[ 6], wA.y, hd2); fma2(acc[ 7], wA.y, hd3);
        fma2(acc[ 8], wB.x, hd0); fma2(acc[ 9], wB.x, hd1); fma2(acc[10], wB.x, hd2); fma2(acc[11], wB.x, hd3);
        fma2(acc[12], wB.y, hd0); fma2(acc[13], wB.y, hd1); fma2(acc[14], wB.y, hd2); fma2(acc[15], wB.y, hd3);

        h4 = h4n; wA = wAn; wB = wBn;
    }
}

template<int K_IN>
__device__ void run_layer(int layer, const float* __restrict__ xT,
                          const float* __restrict__ h0l, const float* __restrict__ c0l,
                          const float* __restrict__ w_ih, const float* __restrict__ w_hh,
                          const float* __restrict__ b_ih, const float* __restrict__ b_hh,
                          float* __restrict__ out, float* smem, unsigned &fb_expect)
{
    constexpr int XC = K_IN / 128;           // x chunks (2 or 4)
    constexpr int NC = XC + 4;               // total chunks (6 or 8)
    constexpr int NP = NC / 2;               // chunk pairs (3 or 4)
    constexpr int XP = XC / 2;               // x pairs (1 or 2)
    constexpr int K_TOT = K_IN + HID;

    float* w_s   = smem + OFF_W;
    float* hbuf  = smem + OFF_HBUF;
    float* red_f = smem + OFF_RED;
    unsigned long long* red_u = (unsigned long long*)red_f;
    float* bias_s = smem + OFF_BIAS;

    const int tid = threadIdx.x;
    const int bg  = blockIdx.x & 1;          // batch half
    const int hg  = blockIdx.x >> 1;         // hidden group (8 units)

    // compute roles: warp = split-K group
    const int kc = tid >> 5;                 // 0..7
    const int rg = (tid >> 3) & 3;           // 0..3 (row-pair quads)
    const int bp = tid & 7;                  // 0..7 (4-batch groups)

    // epilogue roles: one cell each
    const int jj = tid >> 5;                 // 0..7 hidden unit in group
    const int bl = tid & 31;                 // local batch

    unsigned* prod = g_prod + bg * 16;

    // ---- init ----
    full_barrier(fb_expect);
    if (tid < 32) g_prod[tid] = 0;

#pragma unroll 1
    for (int rr = 0; rr < ROWS; ++rr) {
        int row = (rr >> 3) * HID + hg * 8 + (rr & 7);    // gate*H + j
        for (int kg = tid; kg < K_TOT; kg += NTHR) {
            float v = (kg < K_IN) ? w_ih[row * K_IN + kg]
                                  : w_hh[row * HID + (kg - K_IN)];
            w_s[kg * 32 + rr] = v;
        }
    }
    if (tid < 32) {
        int row = (tid >> 3) * HID + hg * 8 + (tid & 7);
        bias_s[tid] = b_ih[row] + b_hh[row];
    }
    float c_reg;
    {
        int j = hg * 8 + jj, b = bg * 32 + bl;
        c_reg = c0l[b * HID + j];
        g_hT[j * 64 + b] = h0l[b * HID + j];      // buffer 0
    }
    full_barrier(fb_expect);

    // prefetch step-0 pair 0 (x chunks 0,1)
    {
        const float* x0 = xT + bg * 32;
        issue_chunk(hbuf + 0 * 4096, x0, tid);
        issue_chunk(hbuf + 1 * 4096, x0 + (size_t)128 * 64, tid);
    }

    for (int t = 0; t < T_STEPS; ++t) {
        const float* xt   = xT + (size_t)t * K_IN * 64 + bg * 32;
        const float* hcur = g_hT + (t & 1) * HID * 64 + bg * 32;

        unsigned long long acc[16];
#pragma unroll
        for (int j = 0; j < 16; ++j) acc[j] = 0ull;

        const int hb_off = kc * 16 * 32 + bp * 4;

#pragma unroll 1
        for (int p = 0; p < NP; ++p) {
            const bool top_issue = (p + 1 < NP) && (p + 1 != XP);
            if (top_issue) {
                int c0 = 2 * (p + 1);
                int c1 = c0 + 1;
                const float* s0 = (c0 < XC) ? (xt + (size_t)c0 * 128 * 64)
                                            : (hcur + (size_t)(c0 - XC) * 128 * 64);
                const float* s1 = (c1 < XC) ? (xt + (size_t)c1 * 128 * 64)
                                            : (hcur + (size_t)(c1 - XC) * 128 * 64);
                issue_chunk(hbuf + (c0 & 3) * 4096, s0, tid);
                issue_chunk(hbuf + (c1 & 3) * 4096, s1, tid);
                cp_wait<2>();
            } else {
                cp_wait<0>();
            }
            __syncthreads();

            if (p == XP - 1) {
                // first chunk of boundary pair covers the prod-wait
                compute_chunk(hbuf + ((2 * p) & 3) * 4096 + hb_off,
                              w_s + ((2 * p) * 128 + kc * 16) * 32 + rg * 8, acc);
                if (t > 0) {
                    if (tid == 0) {
                        unsigned rounds = (unsigned)(t >> 4) + 1u - (((t & 15) == 0) ? 1u : 0u);
                        wait_ge(&prod[t & 15], 64u * rounds);
                    }
                    __syncthreads();
                }
                // issue first h pair (chunks 2XP, 2XP+1)
                {
                    int c0 = 2 * XP, c1 = c0 + 1;
                    issue_chunk(hbuf + (c0 & 3) * 4096, hcur + (size_t)(c0 - XC) * 128 * 64, tid);
                    issue_chunk(hbuf + (c1 & 3) * 4096, hcur + (size_t)(c1 - XC) * 128 * 64, tid);
                }
                compute_chunk(hbuf + ((2 * p + 1) & 3) * 4096 + hb_off,
                              w_s + ((2 * p + 1) * 128 + kc * 16) * 32 + rg * 8, acc);
            } else {
                compute_chunk(hbuf + ((2 * p) & 3) * 4096 + hb_off,
                              w_s + ((2 * p) * 128 + kc * 16) * 32 + rg * 8, acc);
                compute_chunk(hbuf + ((2 * p + 1) & 3) * 4096 + hb_off,
                              w_s + ((2 * p + 1) * 128 + kc * 16) * 32 + rg * 8, acc);
            }
        }

        // ---- reduction: store packed u64 partials ----
#pragma unroll
        for (int rp = 0; rp < 4; ++rp) {
#pragma unroll
            for (int bi = 0; bi < 4; ++bi)
                red_u[(kc * 16 + rg * 4 + rp) * 33 + bp * 4 + bi] = acc[rp * 4 + bi];
        }
        __syncthreads();

        // prefetch next step's pair 0 (slots 0,1; all reads of them synced above)
        if (t + 1 < T_STEPS) {
            const float* xn = xT + (size_t)(t + 1) * K_IN * 64 + bg * 32;
            issue_chunk(hbuf + 0 * 4096, xn, tid);
            issue_chunk(hbuf + 1 * 4096, xn + (size_t)128 * 64, tid);
        }

        // ---- gates: 1 cell per thread ----
        float hn, cn;
        {
            float s0 = bias_s[jj], s1 = bias_s[8 + jj], s2 = bias_s[16 + jj], s3 = bias_s[24 + jj];
            const int lane = bl * 2 + (jj & 1);
            const int rphi = jj >> 1;
#pragma unroll
            for (int k8 = 0; k8 < 8; ++k8) {
                s0 += red_f[(k8 * 16 +      rphi) * 66 + lane];
                s1 += red_f[(k8 * 16 +  4 + rphi) * 66 + lane];
                s2 += red_f[(k8 * 16 +  8 + rphi) * 66 + lane];
                s3 += red_f[(k8 * 16 + 12 + rphi) * 66 + lane];
            }
            cn = sigf(s1) * c_reg + sigf(s0) * tanh_fast(s2);
            hn = sigf(s3) * tanh_fast(cn);
            c_reg = cn;
        }

        // ---- write h_{t+1} (safe: prod[t] observed ⟹ all h_{t-1} reads done) ----
        {
            int j = hg * 8 + jj, b = bg * 32 + bl;
            g_hT[((t + 1) & 1) * HID * 64 + j * 64 + b] = hn;
            if (layer == 0)
                g_hs[((size_t)t * HID + j) * 64 + b] = hn;
            if (t == T_STEPS - 1) {
                out[layer * BATCH * HID + b * HID + j] = hn;
                out[2 * BATCH * HID + layer * BATCH * HID + b * HID + j] = cn;
            }
        }
        __syncthreads();
        if (tid == 0) arrive(&prod[(t + 1) & 15]);
    }

    full_barrier(fb_expect);
}

__global__ void __launch_bounds__(NTHR, 1)
lstm_scan_kernel(const float* __restrict__ h0,
                 const float* __restrict__ c0,
                 const float* __restrict__ w_ih0, const float* __restrict__ w_hh0,
                 const float* __restrict__ b_ih0, const float* __restrict__ b_hh0,
                 const float* __restrict__ w_ih1, const float* __restrict__ w_hh1,
                 const float* __restrict__ b_ih1, const float* __restrict__ b_hh1,
                 float* __restrict__ out)
{
    extern __shared__ float smem[];
    unsigned fb_expect = g_fb_base;

    run_layer<IN0>(0, g_xT, h0, c0, w_ih0, w_hh0, b_ih0, b_hh0, out, smem, fb_expect);
    run_layer<HID>(1, g_hs, h0 + BATCH * HID, c0 + BATCH * HID,
                   w_ih1, w_hh1, b_ih1, b_hh1, out, smem, fb_expect);

    if (blockIdx.x == 0 && threadIdx.x == 0)
        g_fb_base = fb_expect;
}

// -------- prepass: transpose inputs to g_xT AND copy passthrough to out tail --------
__global__ void prep_kernel(const float* __restrict__ in, float* __restrict__ out_tail)
{
    __shared__ float tile[32][33];
    int t  = blockIdx.x;
    int i0 = blockIdx.y * 32;
    int b0 = blockIdx.z * 32;
    int tx = threadIdx.x, ty = threadIdx.y;   // 32 x 8
    const float* ip = in + (size_t)t * BATCH * IN0;
    float* cp = out_tail + (size_t)t * BATCH * IN0;
    float* op = g_xT + (size_t)t * IN0 * BATCH;
#pragma unroll
    for (int yy = 0; yy < 32; yy += 8) {
        float v = ip[(b0 + ty + yy) * IN0 + i0 + tx];
        tile[ty + yy][tx] = v;
        cp[(b0 + ty + yy) * IN0 + i0 + tx] = v;
    }
    __syncthreads();
#pragma unroll
    for (int yy = 0; yy < 32; yy += 8)
        op[(i0 + ty + yy) * BATCH + b0 + tx] = tile[tx][ty + yy];
}

extern "C" void kernel_launch(void* const* d_in, const int* in_sizes, int n_in,
                              void* d_out, int out_size)
{
    const float* inputs = (const float*)d_in[0];
    const float* h0     = (const float*)d_in[1];
    const float* c0     = (const float*)d_in[2];
    const float* w_ih0  = (const float*)d_in[3];
    const float* w_hh0  = (const float*)d_in[4];
    const float* b_ih0  = (const float*)d_in[5];
    const float* b_hh0  = (const float*)d_in[6];
    const float* w_ih1  = (const float*)d_in[7];
    const float* w_hh1  = (const float*)d_in[8];
    const float* b_ih1  = (const float*)d_in[9];
    const float* b_hh1  = (const float*)d_in[10];
    float* out = (float*)d_out;

    (void)in_sizes; (void)n_in; (void)out_size;

    cudaFuncSetAttribute(lstm_scan_kernel,
                         cudaFuncAttributeMaxDynamicSharedMemorySize,
                         SMEM_FLOATS * (int)sizeof(float));

    prep_kernel<<<dim3(T_STEPS, IN0 / 32, BATCH / 32), dim3(32, 8)>>>(
        inputs, out + 4 * BATCH * HID);

    lstm_scan_kernel<<<NBLK, NTHR, SMEM_FLOATS * sizeof(float)>>>(
        h0, c0,
        w_ih0, w_hh0, b_ih0, b_hh0,
        w_ih1, w_hh1, b_ih1, b_hh1,
        out);
}